// round 4
// baseline (speedup 1.0000x reference)
#include <cuda_runtime.h>
#include <cstddef>

#define HID 4096
#define NH 32
#define NKV 8
#define DH 128
#define II 12288
#define SS 8192
#define REP (NH / NKV)
#define EPS 1e-6f
#define PADF 132   // padded row stride (floats) for 64x128 smem tiles

// ---------------- scratch (device globals; no allocation allowed) ----------------
__device__ float g_h[HID];
__device__ float g_qkv[NH*DH + 2*NKV*DH]; // q (4096), k (1024), v (1024)
__device__ float g_q[NH*DH];
__device__ float g_knew[NKV*DH];
__device__ float g_escores[NH*SS];        // exp(score) (unnormalized)
__device__ float g_ssum[NH];              // per-head exp sums
__device__ float g_attnout[NH*DH];
__device__ float g_h1[HID];
__device__ float g_h2[HID];
__device__ float g_act[II];

// ---------------- warp-level dot over a row; n4 MUST be a multiple of 128 ----------------
__device__ __forceinline__ float warp_row_dot(const float4* __restrict__ Wr,
                                              const float4* __restrict__ x4,
                                              int n4, int lane) {
    float a0 = 0.f, a1 = 0.f, a2 = 0.f, a3 = 0.f;
    #pragma unroll 1
    for (int i = lane; i < n4; i += 128) {
        float4 w0 = Wr[i];
        float4 w1 = Wr[i + 32];
        float4 w2 = Wr[i + 64];
        float4 w3 = Wr[i + 96];
        float4 v0 = __ldg(&x4[i]);
        float4 v1 = __ldg(&x4[i + 32]);
        float4 v2 = __ldg(&x4[i + 64]);
        float4 v3 = __ldg(&x4[i + 96]);
        a0 += w0.x*v0.x + w0.y*v0.y + w0.z*v0.z + w0.w*v0.w;
        a1 += w1.x*v1.x + w1.y*v1.y + w1.z*v1.z + w1.w*v1.w;
        a2 += w2.x*v2.x + w2.y*v2.y + w2.z*v2.z + w2.w*v2.w;
        a3 += w3.x*v3.x + w3.y*v3.y + w3.z*v3.z + w3.w*v3.w;
    }
    float s = (a0 + a1) + (a2 + a3);
    #pragma unroll
    for (int o = 16; o; o >>= 1) s += __shfl_xor_sync(0xffffffffu, s, o);
    return s;
}

// ---------------- RMSNorm (single block, 256 threads) + optional zeroing ----------------
__global__ void rmsnorm_kernel(const float* __restrict__ x, const float* __restrict__ w,
                               float* __restrict__ out, int n,
                               float* __restrict__ zbuf, int zn,
                               float* __restrict__ zbuf2, int zn2) {
    if (zbuf)  for (int i = threadIdx.x; i < zn;  i += 256) zbuf[i]  = 0.f;
    if (zbuf2) for (int i = threadIdx.x; i < zn2; i += 256) zbuf2[i] = 0.f;
    __shared__ float red[8];
    __shared__ float s_inv;
    float ss = 0.f;
    for (int i = threadIdx.x; i < n; i += 256) { float v = x[i]; ss += v * v; }
    for (int o = 16; o; o >>= 1) ss += __shfl_xor_sync(0xffffffffu, ss, o);
    int warp = threadIdx.x >> 5, lane = threadIdx.x & 31;
    if (lane == 0) red[warp] = ss;
    __syncthreads();
    if (threadIdx.x == 0) {
        float t = 0.f;
        #pragma unroll
        for (int i = 0; i < 8; i++) t += red[i];
        s_inv = rsqrtf(t / (float)n + EPS);
    }
    __syncthreads();
    float inv = s_inv;
    for (int i = threadIdx.x; i < n; i += 256) out[i] = x[i] * inv * w[i];
}

// ---------------- warp-per-row GEMV: y[row] = W[row,:]·x (+ addv[row]) ----------------
__global__ void gemv_warp_kernel(const float* __restrict__ W, const float* __restrict__ x,
                                 const float* __restrict__ addv, float* __restrict__ y,
                                 int cols, int rows) {
    int warp = threadIdx.x >> 5, lane = threadIdx.x & 31;
    int row = blockIdx.x * 8 + warp;
    if (row >= rows) return;
    const float4* Wr = (const float4*)(W + (size_t)row * cols);
    float s = warp_row_dot(Wr, (const float4*)x, cols >> 2, lane);
    if (lane == 0) y[row] = s + (addv ? addv[row] : 0.f);
}

// ---------------- merged QKV GEMV ----------------
__global__ void qkv_gemv_kernel(const float* __restrict__ Wq, const float* __restrict__ Wk,
                                const float* __restrict__ Wv, const float* __restrict__ x,
                                float* __restrict__ y) {
    int warp = threadIdx.x >> 5, lane = threadIdx.x & 31;
    int row = blockIdx.x * 8 + warp;
    const float* W;
    int r;
    if (row < NH * DH)                 { W = Wq; r = row; }
    else if (row < NH * DH + NKV * DH) { W = Wk; r = row - NH * DH; }
    else                               { W = Wv; r = row - NH * DH - NKV * DH; }
    const float4* Wr = (const float4*)(W + (size_t)r * HID);
    float s = warp_row_dot(Wr, (const float4*)x, HID >> 2, lane);
    if (lane == 0) y[row] = s;
}

// ---------------- warp-per-row fused SwiGLU ----------------
__global__ void glu_warp_kernel(const float* __restrict__ Wg, const float* __restrict__ Wu,
                                const float* __restrict__ x, float* __restrict__ act, int cols) {
    int warp = threadIdx.x >> 5, lane = threadIdx.x & 31;
    int row = blockIdx.x * 8 + warp;
    const float4* g4 = (const float4*)(Wg + (size_t)row * cols);
    const float4* u4 = (const float4*)(Wu + (size_t)row * cols);
    const float4* x4 = (const float4*)x;
    int n4 = cols >> 2;
    float ag0 = 0.f, ag1 = 0.f, au0 = 0.f, au1 = 0.f;
    #pragma unroll 1
    for (int i = lane; i < n4; i += 64) {
        float4 w0 = g4[i];
        float4 w1 = g4[i + 32];
        float4 u0 = u4[i];
        float4 u1 = u4[i + 32];
        float4 v0 = __ldg(&x4[i]);
        float4 v1 = __ldg(&x4[i + 32]);
        ag0 += w0.x*v0.x + w0.y*v0.y + w0.z*v0.z + w0.w*v0.w;
        ag1 += w1.x*v1.x + w1.y*v1.y + w1.z*v1.z + w1.w*v1.w;
        au0 += u0.x*v0.x + u0.y*v0.y + u0.z*v0.z + u0.w*v0.w;
        au1 += u1.x*v1.x + u1.y*v1.y + u1.z*v1.z + u1.w*v1.w;
    }
    float sg = ag0 + ag1, su = au0 + au1;
    #pragma unroll
    for (int o = 16; o; o >>= 1) {
        sg += __shfl_xor_sync(0xffffffffu, sg, o);
        su += __shfl_xor_sync(0xffffffffu, su, o);
    }
    if (lane == 0) {
        float s = sg / (1.f + expf(-sg));
        act[row] = s * su;
    }
}

// ---------------- per-head RMSNorm + RoPE ----------------
__global__ void rope_kernel(const float* __restrict__ qkv, const float* __restrict__ cosv,
                            const float* __restrict__ sinv, const float* __restrict__ qw,
                            const float* __restrict__ kw, float* __restrict__ qout,
                            float* __restrict__ kout) {
    int h = blockIdx.x, t = threadIdx.x;
    const float* src; float* dst; const float* w;
    if (h < NH) { src = qkv + h * DH; dst = qout + h * DH; w = qw; }
    else        { src = qkv + NH * DH + (h - NH) * DH; dst = kout + (h - NH) * DH; w = kw; }
    float v = src[t];
    float ss = v * v;
    for (int o = 16; o; o >>= 1) ss += __shfl_xor_sync(0xffffffffu, ss, o);
    __shared__ float red[4];
    __shared__ float s_inv;
    __shared__ float sh[DH];
    if ((t & 31) == 0) red[t >> 5] = ss;
    __syncthreads();
    if (t == 0) s_inv = rsqrtf((red[0] + red[1] + red[2] + red[3]) * (1.f / DH) + EPS);
    __syncthreads();
    float xn = v * s_inv * w[t];
    sh[t] = xn;
    __syncthreads();
    float rot = (t < DH / 2) ? -sh[t + DH / 2] : sh[t - DH / 2];
    dst[t] = xn * cosv[t] + rot * sinv[t];
}

// ---------------- fused: K-cache copy + exp(scores) + per-head sum ----------------
// grid (SS/64, NKV), 256 threads. SMEM-tiled, no shuffle on dot path.
__global__ void score_kernel(const float* __restrict__ k_cache, const float* __restrict__ knew,
                             const float* __restrict__ q, const float* __restrict__ position,
                             float* __restrict__ out_k, float* __restrict__ escores,
                             float* __restrict__ ssum) {
    __shared__ float kt[64 * PADF];
    __shared__ float qs[REP * PADF];
    int hk = blockIdx.y, s0 = blockIdx.x * 64, t = threadIdx.x;
    int pos = (int)__ldg(position);
    // load 4 q heads into smem
    if (t < REP * 32) {
        int h = t >> 5, c4 = t & 31;
        float4 v = ((const float4*)(q + (hk * REP + h) * DH))[c4];
        *(float4*)(qs + h * PADF + c4 * 4) = v;
    }
    // stream K tile: gmem -> smem + out_k   (8 independent float4 loads per thread)
    #pragma unroll
    for (int j = 0; j < 8; j++) {
        int idx = t + j * 256;
        int row = idx >> 5, c4 = idx & 31;
        int s = s0 + row;
        const float* src = (s == pos) ? (knew + hk * DH)
                                      : (k_cache + ((size_t)hk * SS + s) * DH);
        float4 v = ((const float4*)src)[c4];
        *(float4*)(kt + row * PADF + c4 * 4) = v;
        ((float4*)(out_k + ((size_t)hk * SS + s) * DH))[c4] = v;
    }
    __syncthreads();
    // thread (h, s_local): dot from smem
    int h = t >> 6, sl = t & 63;
    int s = s0 + sl;
    const float4* krow = (const float4*)(kt + sl * PADF);
    const float4* qrow = (const float4*)(qs + h * PADF);
    float a0 = 0.f, a1 = 0.f, a2 = 0.f, a3 = 0.f;
    #pragma unroll
    for (int i = 0; i < 32; i += 4) {
        float4 k0 = krow[i],   q0 = qrow[i];
        float4 k1 = krow[i+1], q1 = qrow[i+1];
        float4 k2 = krow[i+2], q2 = qrow[i+2];
        float4 k3 = krow[i+3], q3 = qrow[i+3];
        a0 += k0.x*q0.x + k0.y*q0.y + k0.z*q0.z + k0.w*q0.w;
        a1 += k1.x*q1.x + k1.y*q1.y + k1.z*q1.z + k1.w*q1.w;
        a2 += k2.x*q2.x + k2.y*q2.y + k2.z*q2.z + k2.w*q2.w;
        a3 += k3.x*q3.x + k3.y*q3.y + k3.z*q3.z + k3.w*q3.w;
    }
    float d = (a0 + a1) + (a2 + a3);
    const float scale = 0.08838834764831845f; // 128^-0.5
    // scores bounded (|q|,|k| ~ sqrt(128)) -> exp without max-subtraction is safe
    float e = (s > pos) ? 0.f : expf(d * scale);
    escores[(size_t)(hk * REP + h) * SS + s] = e;   // coalesced: warp = 32 consecutive s
    float r = e;
    #pragma unroll
    for (int o = 16; o; o >>= 1) r += __shfl_xor_sync(0xffffffffu, r, o);
    if ((t & 31) == 0) atomicAdd(&ssum[hk * REP + h], r);
}

// ---------------- fused: V-cache copy + (attn/sum)·V ----------------
// grid (SS/64, NKV), 256 threads. SMEM-tiled; weights pre-scaled by 1/ssum.
__global__ void av_kernel(const float* __restrict__ v_cache, const float* __restrict__ vnew,
                          const float* __restrict__ escores, const float* __restrict__ ssum,
                          const float* __restrict__ position,
                          float* __restrict__ out_v, float* __restrict__ attnout) {
    __shared__ float vt[64 * PADF];
    __shared__ float es[REP * 64];
    int hk = blockIdx.y, s0 = blockIdx.x * 64, t = threadIdx.x;
    int pos = (int)__ldg(position);
    // load attention weights for this tile, normalized
    {
        int h = t >> 6, sl = t & 63;
        float inv = 1.f / __ldg(&ssum[hk * REP + h]);
        es[h * 64 + sl] = __ldg(&escores[(size_t)(hk * REP + h) * SS + s0 + sl]) * inv;
    }
    // stream V tile: gmem -> smem + out_v
    #pragma unroll
    for (int j = 0; j < 8; j++) {
        int idx = t + j * 256;
        int row = idx >> 5, c4 = idx & 31;
        int s = s0 + row;
        const float* src = (s == pos) ? (vnew + hk * DH)
                                      : (v_cache + ((size_t)hk * SS + s) * DH);
        float4 v = ((const float4*)src)[c4];
        *(float4*)(vt + row * PADF + c4 * 4) = v;
        ((float4*)(out_v + ((size_t)hk * SS + s) * DH))[c4] = v;
    }
    __syncthreads();
    // thread (h, d2): accumulate over 64 s positions
    int h = t >> 6, d2 = t & 63;
    float ax = 0.f, ay = 0.f;
    const float* esh = es + h * 64;
    #pragma unroll 8
    for (int s = 0; s < 64; s++) {
        float a = esh[s];
        float2 v = *(const float2*)(vt + s * PADF + d2 * 2);
        ax += a * v.x; ay += a * v.y;
    }
    float* dst = attnout + (hk * REP + h) * DH + d2 * 2;
    atomicAdd(dst,     ax);
    atomicAdd(dst + 1, ay);
}

// ---------------- host ----------------
extern "C" void kernel_launch(void* const* d_in, const int* in_sizes, int n_in,
                              void* d_out, int out_size) {
    const float* x        = (const float*)d_in[0];
    const float* position = (const float*)d_in[1];
    const float* cosv     = (const float*)d_in[2];
    const float* sinv     = (const float*)d_in[3];
    const float* k_cache  = (const float*)d_in[4];
    const float* v_cache  = (const float*)d_in[5];
    const float* Wq       = (const float*)d_in[6];
    const float* Wk       = (const float*)d_in[7];
    const float* Wv       = (const float*)d_in[8];
    const float* Wo       = (const float*)d_in[9];
    const float* Wg       = (const float*)d_in[10];
    const float* Wu       = (const float*)d_in[11];
    const float* Wd       = (const float*)d_in[12];
    const float* q_norm_w = (const float*)d_in[13];
    const float* k_norm_w = (const float*)d_in[14];
    const float* ln1_w    = (const float*)d_in[15];
    const float* ln2_w    = (const float*)d_in[16];

    float* out     = (float*)d_out;
    float* out_hid = out;
    float* out_k   = out + HID;
    float* out_v   = out + HID + (size_t)NKV * SS * DH;

    float *p_h, *p_qkv, *p_q, *p_knew, *p_es, *p_ssum, *p_attnout, *p_h1, *p_h2, *p_act;
    cudaGetSymbolAddress((void**)&p_h, g_h);
    cudaGetSymbolAddress((void**)&p_qkv, g_qkv);
    cudaGetSymbolAddress((void**)&p_q, g_q);
    cudaGetSymbolAddress((void**)&p_knew, g_knew);
    cudaGetSymbolAddress((void**)&p_es, g_escores);
    cudaGetSymbolAddress((void**)&p_ssum, g_ssum);
    cudaGetSymbolAddress((void**)&p_attnout, g_attnout);
    cudaGetSymbolAddress((void**)&p_h1, g_h1);
    cudaGetSymbolAddress((void**)&p_h2, g_h2);
    cudaGetSymbolAddress((void**)&p_act, g_act);

    // 1. rmsnorm(ln1) + zero attnout & ssum
    rmsnorm_kernel<<<1, 256>>>(x, ln1_w, p_h, HID, p_attnout, NH * DH, p_ssum, NH);
    // 2. merged QKV GEMV
    qkv_gemv_kernel<<<(NH * DH + 2 * NKV * DH) / 8, 256>>>(Wq, Wk, Wv, p_h, p_qkv);
    // 3. per-head norm + rope
    rope_kernel<<<NH + NKV, DH>>>(p_qkv, cosv, sinv, q_norm_w, k_norm_w, p_q, p_knew);
    // 4. K-cache copy + exp(scores) + sums
    score_kernel<<<dim3(SS / 64, NKV), 256>>>(k_cache, p_knew, p_q, position, out_k, p_es, p_ssum);
    // 5. V-cache copy + attn·V (normalized)
    av_kernel<<<dim3(SS / 64, NKV), 256>>>(v_cache, p_qkv + NH * DH + NKV * DH, p_es, p_ssum,
                                           position, out_v, p_attnout);
    // 6. Wo GEMV + residual
    gemv_warp_kernel<<<HID / 8, 256>>>(Wo, p_attnout, x, p_h1, NH * DH, HID);
    // 7. rmsnorm(ln2)
    rmsnorm_kernel<<<1, 256>>>(p_h1, ln2_w, p_h2, HID, nullptr, 0, nullptr, 0);
    // 8. fused SwiGLU GEMV
    glu_warp_kernel<<<II / 8, 256>>>(Wg, Wu, p_h2, p_act, HID);
    // 9. Wd GEMV + residual -> out
    gemv_warp_kernel<<<HID / 8, 256>>>(Wd, p_act, p_h1, out_hid, II, HID);
}

// round 6
// speedup vs baseline: 1.0434x; 1.0434x over previous
#include <cuda_runtime.h>
#include <cstddef>

#define HID 4096
#define NH 32
#define NKV 8
#define DH 128
#define II 12288
#define SS 8192
#define REP (NH / NKV)
#define EPS 1e-6f
#define PADF 132   // padded row stride (floats) for 64x128 smem tiles

// ---------------- scratch (device globals; no allocation allowed) ----------------
__device__ float g_h[HID];
__device__ float g_qkv[NH*DH + 2*NKV*DH]; // q (4096), k (1024), v (1024)
__device__ float g_q[NH*DH];
__device__ float g_knew[NKV*DH];
__device__ float g_escores[NH*SS];        // exp(score) (unnormalized)
__device__ float g_ssum[NH];              // per-head exp sums
__device__ float g_attnout[NH*DH];
__device__ float g_h1[HID];
__device__ float g_h2[HID];
__device__ float g_act[II];

// ---------------- warp-level dot over a row; n4 MUST be a multiple of 128 ----------------
__device__ __forceinline__ float warp_row_dot(const float4* __restrict__ Wr,
                                              const float4* __restrict__ x4,
                                              int n4, int lane) {
    float a0 = 0.f, a1 = 0.f, a2 = 0.f, a3 = 0.f;
    #pragma unroll 1
    for (int i = lane; i < n4; i += 128) {
        float4 w0 = Wr[i];
        float4 w1 = Wr[i + 32];
        float4 w2 = Wr[i + 64];
        float4 w3 = Wr[i + 96];
        float4 v0 = __ldg(&x4[i]);
        float4 v1 = __ldg(&x4[i + 32]);
        float4 v2 = __ldg(&x4[i + 64]);
        float4 v3 = __ldg(&x4[i + 96]);
        a0 += w0.x*v0.x + w0.y*v0.y + w0.z*v0.z + w0.w*v0.w;
        a1 += w1.x*v1.x + w1.y*v1.y + w1.z*v1.z + w1.w*v1.w;
        a2 += w2.x*v2.x + w2.y*v2.y + w2.z*v2.z + w2.w*v2.w;
        a3 += w3.x*v3.x + w3.y*v3.y + w3.z*v3.z + w3.w*v3.w;
    }
    float s = (a0 + a1) + (a2 + a3);
    #pragma unroll
    for (int o = 16; o; o >>= 1) s += __shfl_xor_sync(0xffffffffu, s, o);
    return s;
}

// ---------------- RMSNorm (single block, 256 threads) + optional zeroing ----------------
__global__ void rmsnorm_kernel(const float* __restrict__ x, const float* __restrict__ w,
                               float* __restrict__ out, int n,
                               float* __restrict__ zbuf, int zn,
                               float* __restrict__ zbuf2, int zn2) {
    if (zbuf)  for (int i = threadIdx.x; i < zn;  i += 256) zbuf[i]  = 0.f;
    if (zbuf2) for (int i = threadIdx.x; i < zn2; i += 256) zbuf2[i] = 0.f;
    __shared__ float red[8];
    __shared__ float s_inv;
    float ss = 0.f;
    for (int i = threadIdx.x; i < n; i += 256) { float v = x[i]; ss += v * v; }
    for (int o = 16; o; o >>= 1) ss += __shfl_xor_sync(0xffffffffu, ss, o);
    int warp = threadIdx.x >> 5, lane = threadIdx.x & 31;
    if (lane == 0) red[warp] = ss;
    __syncthreads();
    if (threadIdx.x == 0) {
        float t = 0.f;
        #pragma unroll
        for (int i = 0; i < 8; i++) t += red[i];
        s_inv = rsqrtf(t / (float)n + EPS);
    }
    __syncthreads();
    float inv = s_inv;
    for (int i = threadIdx.x; i < n; i += 256) out[i] = x[i] * inv * w[i];
}

// ---------------- warp-per-row GEMV: y[row] = W[row,:]·x (+ addv[row]) ----------------
__global__ void gemv_warp_kernel(const float* __restrict__ W, const float* __restrict__ x,
                                 const float* __restrict__ addv, float* __restrict__ y,
                                 int cols, int rows) {
    int warp = threadIdx.x >> 5, lane = threadIdx.x & 31;
    int row = blockIdx.x * 8 + warp;
    if (row >= rows) return;
    const float4* Wr = (const float4*)(W + (size_t)row * cols);
    float s = warp_row_dot(Wr, (const float4*)x, cols >> 2, lane);
    if (lane == 0) y[row] = s + (addv ? addv[row] : 0.f);
}

// ---------------- merged QKV GEMV ----------------
__global__ void qkv_gemv_kernel(const float* __restrict__ Wq, const float* __restrict__ Wk,
                                const float* __restrict__ Wv, const float* __restrict__ x,
                                float* __restrict__ y) {
    int warp = threadIdx.x >> 5, lane = threadIdx.x & 31;
    int row = blockIdx.x * 8 + warp;
    const float* W;
    int r;
    if (row < NH * DH)                 { W = Wq; r = row; }
    else if (row < NH * DH + NKV * DH) { W = Wk; r = row - NH * DH; }
    else                               { W = Wv; r = row - NH * DH - NKV * DH; }
    const float4* Wr = (const float4*)(W + (size_t)r * HID);
    float s = warp_row_dot(Wr, (const float4*)x, HID >> 2, lane);
    if (lane == 0) y[row] = s;
}

// ---------------- warp-per-row fused SwiGLU ----------------
__global__ void glu_warp_kernel(const float* __restrict__ Wg, const float* __restrict__ Wu,
                                const float* __restrict__ x, float* __restrict__ act, int cols) {
    int warp = threadIdx.x >> 5, lane = threadIdx.x & 31;
    int row = blockIdx.x * 8 + warp;
    const float4* g4 = (const float4*)(Wg + (size_t)row * cols);
    const float4* u4 = (const float4*)(Wu + (size_t)row * cols);
    const float4* x4 = (const float4*)x;
    int n4 = cols >> 2;
    float ag0 = 0.f, ag1 = 0.f, au0 = 0.f, au1 = 0.f;
    #pragma unroll 1
    for (int i = lane; i < n4; i += 64) {
        float4 w0 = g4[i];
        float4 w1 = g4[i + 32];
        float4 u0 = u4[i];
        float4 u1 = u4[i + 32];
        float4 v0 = __ldg(&x4[i]);
        float4 v1 = __ldg(&x4[i + 32]);
        ag0 += w0.x*v0.x + w0.y*v0.y + w0.z*v0.z + w0.w*v0.w;
        ag1 += w1.x*v1.x + w1.y*v1.y + w1.z*v1.z + w1.w*v1.w;
        au0 += u0.x*v0.x + u0.y*v0.y + u0.z*v0.z + u0.w*v0.w;
        au1 += u1.x*v1.x + u1.y*v1.y + u1.z*v1.z + u1.w*v1.w;
    }
    float sg = ag0 + ag1, su = au0 + au1;
    #pragma unroll
    for (int o = 16; o; o >>= 1) {
        sg += __shfl_xor_sync(0xffffffffu, sg, o);
        su += __shfl_xor_sync(0xffffffffu, su, o);
    }
    if (lane == 0) {
        float s = sg / (1.f + expf(-sg));
        act[row] = s * su;
    }
}

// ---------------- per-head RMSNorm + RoPE ----------------
__global__ void rope_kernel(const float* __restrict__ qkv, const float* __restrict__ cosv,
                            const float* __restrict__ sinv, const float* __restrict__ qw,
                            const float* __restrict__ kw, float* __restrict__ qout,
                            float* __restrict__ kout) {
    int h = blockIdx.x, t = threadIdx.x;
    const float* src; float* dst; const float* w;
    if (h < NH) { src = qkv + h * DH; dst = qout + h * DH; w = qw; }
    else        { src = qkv + NH * DH + (h - NH) * DH; dst = kout + (h - NH) * DH; w = kw; }
    float v = src[t];
    float ss = v * v;
    for (int o = 16; o; o >>= 1) ss += __shfl_xor_sync(0xffffffffu, ss, o);
    __shared__ float red[4];
    __shared__ float s_inv;
    __shared__ float sh[DH];
    if ((t & 31) == 0) red[t >> 5] = ss;
    __syncthreads();
    if (t == 0) s_inv = rsqrtf((red[0] + red[1] + red[2] + red[3]) * (1.f / DH) + EPS);
    __syncthreads();
    float xn = v * s_inv * w[t];
    sh[t] = xn;
    __syncthreads();
    float rot = (t < DH / 2) ? -sh[t + DH / 2] : sh[t - DH / 2];
    dst[t] = xn * cosv[t] + rot * sinv[t];
}

// ---------------- fused: K-cache copy + exp(scores) + per-head sum ----------------
// grid (SS/64, NKV), 256 threads. Phase 1 batches 8 independent LDG.128 before stores.
__global__ void __launch_bounds__(256, 3)
score_kernel(const float* __restrict__ k_cache, const float* __restrict__ knew,
             const float* __restrict__ q, const float* __restrict__ position,
             float* __restrict__ out_k, float* __restrict__ escores,
             float* __restrict__ ssum) {
    __shared__ float kt[64 * PADF];
    __shared__ float qs[REP * PADF];
    int hk = blockIdx.y, s0 = blockIdx.x * 64, t = threadIdx.x;
    int pos = (int)__ldg(position);
    // load 4 q heads into smem
    if (t < REP * 32) {
        int h = t >> 5, c4 = t & 31;
        float4 v = ((const float4*)(q + (hk * REP + h) * DH))[c4];
        *(float4*)(qs + h * PADF + c4 * 4) = v;
    }
    // phase 1: batch all 8 loads (keeps 128B/thread in flight), then store
    {
        float4 v[8];
        #pragma unroll
        for (int j = 0; j < 8; j++) {
            int idx = t + j * 256;
            int row = idx >> 5, c4 = idx & 31;
            int s = s0 + row;
            const float* src = (s == pos) ? (knew + hk * DH)
                                          : (k_cache + ((size_t)hk * SS + s) * DH);
            v[j] = ((const float4*)src)[c4];
        }
        #pragma unroll
        for (int j = 0; j < 8; j++) {
            int idx = t + j * 256;
            int row = idx >> 5, c4 = idx & 31;
            int s = s0 + row;
            *(float4*)(kt + row * PADF + c4 * 4) = v[j];
            ((float4*)(out_k + ((size_t)hk * SS + s) * DH))[c4] = v[j];
        }
    }
    __syncthreads();
    // phase 2: thread (h, s_local) dots from smem
    int h = t >> 6, sl = t & 63;
    int s = s0 + sl;
    const float4* krow = (const float4*)(kt + sl * PADF);
    const float4* qrow = (const float4*)(qs + h * PADF);
    float a0 = 0.f, a1 = 0.f, a2 = 0.f, a3 = 0.f;
    #pragma unroll
    for (int i = 0; i < 32; i += 4) {
        float4 k0 = krow[i],   q0 = qrow[i];
        float4 k1 = krow[i+1], q1 = qrow[i+1];
        float4 k2 = krow[i+2], q2 = qrow[i+2];
        float4 k3 = krow[i+3], q3 = qrow[i+3];
        a0 += k0.x*q0.x + k0.y*q0.y + k0.z*q0.z + k0.w*q0.w;
        a1 += k1.x*q1.x + k1.y*q1.y + k1.z*q1.z + k1.w*q1.w;
        a2 += k2.x*q2.x + k2.y*q2.y + k2.z*q2.z + k2.w*q2.w;
        a3 += k3.x*q3.x + k3.y*q3.y + k3.z*q3.z + k3.w*q3.w;
    }
    float d = (a0 + a1) + (a2 + a3);
    const float scale = 0.08838834764831845f; // 128^-0.5
    // scores bounded (|q|,|k| ~ sqrt(128)) -> exp without max-subtraction is safe
    float e = (s > pos) ? 0.f : expf(d * scale);
    escores[(size_t)(hk * REP + h) * SS + s] = e;   // coalesced: warp = 32 consecutive s
    float r = e;
    #pragma unroll
    for (int o = 16; o; o >>= 1) r += __shfl_xor_sync(0xffffffffu, r, o);
    if ((t & 31) == 0) atomicAdd(&ssum[hk * REP + h], r);
}

// ---------------- fused: V-cache copy + (attn/sum)·V ----------------
// grid (SS/64, NKV), 256 threads. Phase 1 batches 8 independent LDG.128 before stores.
__global__ void __launch_bounds__(256, 3)
av_kernel(const float* __restrict__ v_cache, const float* __restrict__ vnew,
          const float* __restrict__ escores, const float* __restrict__ ssum,
          const float* __restrict__ position,
          float* __restrict__ out_v, float* __restrict__ attnout) {
    __shared__ float vt[64 * PADF];
    __shared__ float es[REP * 64];
    int hk = blockIdx.y, s0 = blockIdx.x * 64, t = threadIdx.x;
    int pos = (int)__ldg(position);
    // attention weights for this tile, normalized
    {
        int h = t >> 6, sl = t & 63;
        float inv = 1.f / __ldg(&ssum[hk * REP + h]);
        es[h * 64 + sl] = __ldg(&escores[(size_t)(hk * REP + h) * SS + s0 + sl]) * inv;
    }
    // phase 1: batch all 8 loads, then store
    {
        float4 v[8];
        #pragma unroll
        for (int j = 0; j < 8; j++) {
            int idx = t + j * 256;
            int row = idx >> 5, c4 = idx & 31;
            int s = s0 + row;
            const float* src = (s == pos) ? (vnew + hk * DH)
                                          : (v_cache + ((size_t)hk * SS + s) * DH);
            v[j] = ((const float4*)src)[c4];
        }
        #pragma unroll
        for (int j = 0; j < 8; j++) {
            int idx = t + j * 256;
            int row = idx >> 5, c4 = idx & 31;
            int s = s0 + row;
            *(float4*)(vt + row * PADF + c4 * 4) = v[j];
            ((float4*)(out_v + ((size_t)hk * SS + s) * DH))[c4] = v[j];
        }
    }
    __syncthreads();
    // phase 2: thread (h, d2) accumulates over 64 s positions
    int h = t >> 6, d2 = t & 63;
    float ax = 0.f, ay = 0.f;
    const float* esh = es + h * 64;
    #pragma unroll 8
    for (int s = 0; s < 64; s++) {
        float a = esh[s];
        float2 v = *(const float2*)(vt + s * PADF + d2 * 2);
        ax += a * v.x; ay += a * v.y;
    }
    float* dst = attnout + (hk * REP + h) * DH + d2 * 2;
    atomicAdd(dst,     ax);
    atomicAdd(dst + 1, ay);
}

// ---------------- host ----------------
extern "C" void kernel_launch(void* const* d_in, const int* in_sizes, int n_in,
                              void* d_out, int out_size) {
    const float* x        = (const float*)d_in[0];
    const float* position = (const float*)d_in[1];
    const float* cosv     = (const float*)d_in[2];
    const float* sinv     = (const float*)d_in[3];
    const float* k_cache  = (const float*)d_in[4];
    const float* v_cache  = (const float*)d_in[5];
    const float* Wq       = (const float*)d_in[6];
    const float* Wk       = (const float*)d_in[7];
    const float* Wv       = (const float*)d_in[8];
    const float* Wo       = (const float*)d_in[9];
    const float* Wg       = (const float*)d_in[10];
    const float* Wu       = (const float*)d_in[11];
    const float* Wd       = (const float*)d_in[12];
    const float* q_norm_w = (const float*)d_in[13];
    const float* k_norm_w = (const float*)d_in[14];
    const float* ln1_w    = (const float*)d_in[15];
    const float* ln2_w    = (const float*)d_in[16];

    float* out     = (float*)d_out;
    float* out_hid = out;
    float* out_k   = out + HID;
    float* out_v   = out + HID + (size_t)NKV * SS * DH;

    float *p_h, *p_qkv, *p_q, *p_knew, *p_es, *p_ssum, *p_attnout, *p_h1, *p_h2, *p_act;
    cudaGetSymbolAddress((void**)&p_h, g_h);
    cudaGetSymbolAddress((void**)&p_qkv, g_qkv);
    cudaGetSymbolAddress((void**)&p_q, g_q);
    cudaGetSymbolAddress((void**)&p_knew, g_knew);
    cudaGetSymbolAddress((void**)&p_es, g_escores);
    cudaGetSymbolAddress((void**)&p_ssum, g_ssum);
    cudaGetSymbolAddress((void**)&p_attnout, g_attnout);
    cudaGetSymbolAddress((void**)&p_h1, g_h1);
    cudaGetSymbolAddress((void**)&p_h2, g_h2);
    cudaGetSymbolAddress((void**)&p_act, g_act);

    // 1. rmsnorm(ln1) + zero attnout & ssum
    rmsnorm_kernel<<<1, 256>>>(x, ln1_w, p_h, HID, p_attnout, NH * DH, p_ssum, NH);
    // 2. merged QKV GEMV
    qkv_gemv_kernel<<<(NH * DH + 2 * NKV * DH) / 8, 256>>>(Wq, Wk, Wv, p_h, p_qkv);
    // 3. per-head norm + rope
    rope_kernel<<<NH + NKV, DH>>>(p_qkv, cosv, sinv, q_norm_w, k_norm_w, p_q, p_knew);
    // 4. K-cache copy + exp(scores) + sums
    score_kernel<<<dim3(SS / 64, NKV), 256>>>(k_cache, p_knew, p_q, position, out_k, p_es, p_ssum);
    // 5. V-cache copy + attn·V (normalized)
    av_kernel<<<dim3(SS / 64, NKV), 256>>>(v_cache, p_qkv + NH * DH + NKV * DH, p_es, p_ssum,
                                           position, out_v, p_attnout);
    // 6. Wo GEMV + residual
    gemv_warp_kernel<<<HID / 8, 256>>>(Wo, p_attnout, x, p_h1, NH * DH, HID);
    // 7. rmsnorm(ln2)
    rmsnorm_kernel<<<1, 256>>>(p_h1, ln2_w, p_h2, HID, nullptr, 0, nullptr, 0);
    // 8. fused SwiGLU GEMV
    glu_warp_kernel<<<II / 8, 256>>>(Wg, Wu, p_h2, p_act, HID);
    // 9. Wd GEMV + residual -> out
    gemv_warp_kernel<<<HID / 8, 256>>>(Wd, p_act, p_h1, out_hid, II, HID);
}